// round 14
// baseline (speedup 1.0000x reference)
#include <cuda_runtime.h>
#include <cuda_bf16.h>
#include <cstdint>

#define N_NODES 10000
#define N_EDGES 640000
#define D_FEAT  128

// Edge split: [0, E_SCAT) handled by scatter warps (sequential reads + fp32
// RED into L2-resident g_agg); [E_SCAT, N_EDGES) bucketed and gathered
// (random 512B reads). The two halves bind DIFFERENT resources (LSU vs DRAM)
// and run concurrently in one kernel via warp specialization.
#define E_SCAT 288000
#define E_GATH (N_EDGES - E_SCAT)      // 352000, gather-degree ~ Poisson(35)
#define CAP 96                          // >10 sigma above mean 35.2

#define GRID_H 313                      // hybrid grid: ceil(10000/32)
#define CHUNK  ((E_SCAT + GRID_H - 1) / GRID_H)   // 921 scatter edges/block

// Zero-invariant device state (.bss zeroed at load; re-zeroed in-kernel after
// use each call, so graph replays always see zeros).
__device__ int   g_cnt[N_NODES];
__device__ int   g_eid2[N_NODES * CAP];            // 3.84 MB
__device__ __align__(16) float g_agg[N_NODES * D_FEAT];  // 5.12 MB

// ---------------------------------------------------------------------------
// helpers
// ---------------------------------------------------------------------------
__device__ __forceinline__ void red_add_v4(float* dst, float4 v) {
    asm volatile("red.global.add.v4.f32 [%0], {%1, %2, %3, %4};"
                 :: "l"(dst), "f"(v.x), "f"(v.y), "f"(v.z), "f"(v.w)
                 : "memory");
}
__device__ __forceinline__ unsigned long long fma2(unsigned long long a,
                                                   unsigned long long b,
                                                   unsigned long long c) {
    unsigned long long d;
    asm("fma.rn.f32x2 %0, %1, %2, %3;" : "=l"(d) : "l"(a), "l"(b), "l"(c));
    return d;
}
__device__ __forceinline__ unsigned long long dup2(float x) {
    unsigned long long d;
    asm("mov.b64 %0, {%1, %1};" : "=l"(d) : "f"(x));
    return d;
}

// ---------------------------------------------------------------------------
// 1. fill buckets for the GATHER half only ([E_SCAT, N_EDGES)).
// ---------------------------------------------------------------------------
__global__ void fill_kernel(const int* __restrict__ recv_idx) {
    int i = blockIdx.x * blockDim.x + threadIdx.x;   // quad index
    if (i < E_GATH / 4) {
        int4 r = reinterpret_cast<const int4*>(recv_idx + E_SCAT)[i];
        int e0 = E_SCAT + i * 4;
        int p0 = atomicAdd(&g_cnt[r.x], 1);
        int p1 = atomicAdd(&g_cnt[r.y], 1);
        int p2 = atomicAdd(&g_cnt[r.z], 1);
        int p3 = atomicAdd(&g_cnt[r.w], 1);
        if (p0 < CAP) g_eid2[r.x * CAP + p0] = e0;
        if (p1 < CAP) g_eid2[r.y * CAP + p1] = e0 + 1;
        if (p2 < CAP) g_eid2[r.z * CAP + p2] = e0 + 2;
        if (p3 < CAP) g_eid2[r.w * CAP + p3] = e0 + 3;
    }
}

// ---------------------------------------------------------------------------
// 2. hybrid aggregation kernel: warps 0-3 gather, warps 4-7 scatter.
//    Both accumulate into g_agg (atomic adds commute).
// ---------------------------------------------------------------------------
#define NT 32

__global__ __launch_bounds__(256) void hybrid_kernel(
    const float* __restrict__ edge_feat,
    const int*   __restrict__ recv_idx)
{
    __shared__ int eidS[4][CAP];
    __shared__ int qctr;

    const int tid  = threadIdx.x;
    const int lane = tid & 31;
    const int wid  = tid >> 5;
    const int bid  = blockIdx.x;
    const int n0   = bid * NT;

    if (tid == 0) qctr = 0;
    __syncthreads();

    if (wid < 4) {
        // ---------------- gather warps ----------------
        for (;;) {
            int pos;
            if (lane == 0) pos = atomicAdd(&qctr, 1);
            pos = __shfl_sync(0xFFFFFFFFu, pos, 0);
            if (pos >= NT) break;

            int gn = n0 + pos;
            if (gn >= N_NODES) continue;

            const int* bucket = g_eid2 + (size_t)gn * CAP;
            int cnt = g_cnt[gn];
            if (cnt > CAP) cnt = CAP;
            for (int base = lane; base < cnt; base += 32)
                eidS[wid][base] = bucket[base];
            __syncwarp();

            float4 acc = make_float4(0.f, 0.f, 0.f, 0.f);
            int t = 0;
            for (; t + 16 <= cnt; t += 16) {
                int ea[8], eb[8];
                #pragma unroll
                for (int u = 0; u < 8; u++) ea[u] = eidS[wid][t + u];
                #pragma unroll
                for (int u = 0; u < 8; u++) eb[u] = eidS[wid][t + 8 + u];
                float4 va[8], vb[8];
                #pragma unroll
                for (int u = 0; u < 8; u++)
                    va[u] = *reinterpret_cast<const float4*>(
                        edge_feat + (size_t)ea[u] * D_FEAT + lane * 4);
                #pragma unroll
                for (int u = 0; u < 8; u++)
                    vb[u] = *reinterpret_cast<const float4*>(
                        edge_feat + (size_t)eb[u] * D_FEAT + lane * 4);
                #pragma unroll
                for (int u = 0; u < 8; u++) {
                    acc.x += va[u].x; acc.y += va[u].y;
                    acc.z += va[u].z; acc.w += va[u].w;
                }
                #pragma unroll
                for (int u = 0; u < 8; u++) {
                    acc.x += vb[u].x; acc.y += vb[u].y;
                    acc.z += vb[u].z; acc.w += vb[u].w;
                }
            }
            for (; t + 4 <= cnt; t += 4) {
                int e[4];
                #pragma unroll
                for (int u = 0; u < 4; u++) e[u] = eidS[wid][t + u];
                float4 v[4];
                #pragma unroll
                for (int u = 0; u < 4; u++)
                    v[u] = *reinterpret_cast<const float4*>(
                        edge_feat + (size_t)e[u] * D_FEAT + lane * 4);
                #pragma unroll
                for (int u = 0; u < 4; u++) {
                    acc.x += v[u].x; acc.y += v[u].y;
                    acc.z += v[u].z; acc.w += v[u].w;
                }
            }
            for (; t < cnt; t++) {
                int e = eidS[wid][t];
                float4 v = *reinterpret_cast<const float4*>(
                    edge_feat + (size_t)e * D_FEAT + lane * 4);
                acc.x += v.x; acc.y += v.y; acc.z += v.z; acc.w += v.w;
            }
            __syncwarp();

            // one RED per node per lane: negligible count, merges with scatter
            red_add_v4(g_agg + (size_t)gn * D_FEAT + lane * 4, acc);
        }
        // all gather warps done reading g_cnt -> warp 0 re-zeros for next call
        asm volatile("bar.sync 1, 128;" ::: "memory");
        if (wid == 0) {
            for (int i = lane; i < NT; i += 32) {
                int gn = n0 + i;
                if (gn < N_NODES) g_cnt[gn] = 0;
            }
        }
    } else {
        // ---------------- scatter warps ----------------
        int sw   = wid - 4;
        int cbeg = bid * CHUNK;
        int cend = cbeg + CHUNK; if (cend > E_SCAT) cend = E_SCAT;
        if (cbeg < cend) {
            int len  = cend - cbeg;
            int q    = (len + 3) >> 2;
            int wbeg = cbeg + sw * q;
            int wend = wbeg + q; if (wend > cend) wend = cend;

            int e = wbeg;
            for (; e + 8 <= wend; e += 8) {
                int nd = (lane < 8) ? recv_idx[e + lane] : 0;
                float4 v[8];
                #pragma unroll
                for (int u = 0; u < 8; u++)
                    v[u] = *reinterpret_cast<const float4*>(
                        edge_feat + (size_t)(e + u) * D_FEAT + lane * 4);
                #pragma unroll
                for (int u = 0; u < 8; u++) {
                    int node = __shfl_sync(0xFFFFFFFFu, nd, u);
                    red_add_v4(g_agg + (size_t)node * D_FEAT + lane * 4, v[u]);
                }
            }
            for (; e < wend; e++) {
                int node = recv_idx[e];
                float4 v = *reinterpret_cast<const float4*>(
                    edge_feat + (size_t)e * D_FEAT + lane * 4);
                red_add_v4(g_agg + (size_t)node * D_FEAT + lane * 4, v);
            }
        }
    }
}

// ---------------------------------------------------------------------------
// 3. GEMM: out = [node_feat | g_agg] @ W + b.  Stages this block's g_agg rows
//    into smem (L2 hits: freshly written) and re-zeros them for the next call.
// ---------------------------------------------------------------------------
#define KC 16

__global__ __launch_bounds__(256) void gemm_kernel(
    const float* __restrict__ node_feat,
    const float* __restrict__ W,
    const float* __restrict__ b,
    float* __restrict__ out)
{
    __shared__ __align__(16) float AggS[NT * D_FEAT];   // 16 KB
    __shared__ __align__(16) float Ws[KC * D_FEAT];     //  8 KB
    __shared__ __align__(16) float Xs[NT * KC];         //  2 KB

    const int tid  = threadIdx.x;
    const int lane = tid & 31;
    const int wid  = tid >> 5;
    const int n0   = blockIdx.x * NT;

    // Stage agg rows + re-zero g_agg (rows are block-private)
    {
        float4* aggv = reinterpret_cast<float4*>(g_agg + (size_t)n0 * D_FEAT);
        float4* aggs = reinterpret_cast<float4*>(AggS);
        const int NF4 = NT * D_FEAT / 4;   // 1024
        #pragma unroll
        for (int i = tid; i < NF4; i += 256) {
            int row = i >> 5;              // / (D_FEAT/4)
            if (n0 + row < N_NODES) {
                aggs[i] = aggv[i];
                aggv[i] = make_float4(0.f, 0.f, 0.f, 0.f);
            } else {
                aggs[i] = make_float4(0.f, 0.f, 0.f, 0.f);
            }
        }
    }
    __syncthreads();

    unsigned long long acc2[4][2];
    #pragma unroll
    for (int i = 0; i < 4; i++) { acc2[i][0] = 0ull; acc2[i][1] = 0ull; }

    // First half: K in [0,128) from node_feat
    for (int k0 = 0; k0 < D_FEAT; k0 += KC) {
        {
            const float4* src = reinterpret_cast<const float4*>(W + k0 * D_FEAT);
            float4* dst = reinterpret_cast<float4*>(Ws);
            dst[tid]       = src[tid];
            dst[tid + 256] = src[tid + 256];
        }
        #pragma unroll
        for (int i = tid; i < NT * KC; i += 256) {
            int n = i >> 4;
            int k = i & (KC - 1);
            int gn = n0 + n;
            Xs[i] = (gn < N_NODES) ? node_feat[(size_t)gn * D_FEAT + k0 + k] : 0.f;
        }
        __syncthreads();
        #pragma unroll
        for (int kk = 0; kk < KC; kk++) {
            const unsigned long long* wrow =
                reinterpret_cast<const unsigned long long*>(&Ws[kk * D_FEAT + lane * 4]);
            unsigned long long wp0 = wrow[0];
            unsigned long long wp1 = wrow[1];
            #pragma unroll
            for (int n = 0; n < 4; n++) {
                unsigned long long xx = dup2(Xs[(wid * 4 + n) * KC + kk]);
                acc2[n][0] = fma2(xx, wp0, acc2[n][0]);
                acc2[n][1] = fma2(xx, wp1, acc2[n][1]);
            }
        }
        __syncthreads();
    }

    // Second half: K in [128,256) from AggS
    for (int k0 = 0; k0 < D_FEAT; k0 += KC) {
        {
            const float4* src = reinterpret_cast<const float4*>(W + (D_FEAT + k0) * D_FEAT);
            float4* dst = reinterpret_cast<float4*>(Ws);
            dst[tid]       = src[tid];
            dst[tid + 256] = src[tid + 256];
        }
        __syncthreads();
        #pragma unroll
        for (int kk = 0; kk < KC; kk++) {
            const unsigned long long* wrow =
                reinterpret_cast<const unsigned long long*>(&Ws[kk * D_FEAT + lane * 4]);
            unsigned long long wp0 = wrow[0];
            unsigned long long wp1 = wrow[1];
            #pragma unroll
            for (int n = 0; n < 4; n++) {
                unsigned long long xx = dup2(AggS[(wid * 4 + n) * D_FEAT + k0 + kk]);
                acc2[n][0] = fma2(xx, wp0, acc2[n][0]);
                acc2[n][1] = fma2(xx, wp1, acc2[n][1]);
            }
        }
        __syncthreads();
    }

    float4 bb = *reinterpret_cast<const float4*>(&b[lane * 4]);
    #pragma unroll
    for (int n = 0; n < 4; n++) {
        int gn = n0 + wid * 4 + n;
        if (gn < N_NODES) {
            float2 p0 = *reinterpret_cast<float2*>(&acc2[n][0]);
            float2 p1 = *reinterpret_cast<float2*>(&acc2[n][1]);
            float4 r;
            r.x = p0.x + bb.x;
            r.y = p0.y + bb.y;
            r.z = p1.x + bb.z;
            r.w = p1.y + bb.w;
            *reinterpret_cast<float4*>(out + (size_t)gn * D_FEAT + lane * 4) = r;
        }
    }
}

// ---------------------------------------------------------------------------
extern "C" void kernel_launch(void* const* d_in, const int* in_sizes, int n_in,
                              void* d_out, int out_size) {
    const float* edge_feat = (const float*)d_in[0];
    const float* node_feat = (const float*)d_in[1];
    const int*   recv_idx  = (const int*)d_in[2];
    const float* W         = (const float*)d_in[3];
    const float* b         = (const float*)d_in[4];
    float*       out       = (float*)d_out;

    fill_kernel<<<(E_GATH / 4 + 255) / 256, 256>>>(recv_idx);
    hybrid_kernel<<<GRID_H, 256>>>(edge_feat, recv_idx);
    gemm_kernel<<<GRID_H, 256>>>(node_feat, W, b, out);
}

// round 15
// speedup vs baseline: 1.1097x; 1.1097x over previous
#include <cuda_runtime.h>
#include <cuda_bf16.h>
#include <cstdint>

#define N_NODES 10000
#define N_EDGES 640000
#define D_FEAT  128

// Padded-bucket CSR (R10 champion architecture).
#define CAP 160

// .bss zeroed at load; g_cnt re-zeroed by fused_kernel each call.
__device__ int g_cnt[N_NODES];
__device__ int g_eid2[N_NODES * CAP];          // 6.4 MB

// ---------------------------------------------------------------------------
// f32x2 helpers
// ---------------------------------------------------------------------------
__device__ __forceinline__ unsigned long long fma2(unsigned long long a,
                                                   unsigned long long b,
                                                   unsigned long long c) {
    unsigned long long d;
    asm("fma.rn.f32x2 %0, %1, %2, %3;" : "=l"(d) : "l"(a), "l"(b), "l"(c));
    return d;
}
__device__ __forceinline__ unsigned long long dup2(float x) {
    unsigned long long d;
    asm("mov.b64 %0, {%1, %1};" : "=l"(d) : "f"(x));
    return d;
}

#define NT 16384   // unused sentinel guard (real NT below)
#undef NT
#define NT 32
#define KC 16

#define FILL_BLOCKS 625                    // 625*256*4 = 640000 edges
#define GEMM_BLOCKS ((N_NODES + NT - 1) / NT)   // 313

// ---------------------------------------------------------------------------
// Kernel 1: block-role specialized.
//   Blocks [0, FILL_BLOCKS): bucket-fill (latency/contention-bound, ~2% issue)
//   Blocks [FILL_BLOCKS, +GEMM_BLOCKS): out = node_feat @ W_top + b
//     (FMA-bound). The two roles use complementary resources and co-reside,
//     so the half-GEMM rides inside fill's idle issue slots.
// ---------------------------------------------------------------------------
__global__ __launch_bounds__(256) void prep_kernel(
    const int*   __restrict__ recv_idx,
    const float* __restrict__ node_feat,
    const float* __restrict__ W,           // [256,128] row-major; top half used
    const float* __restrict__ b,
    float* __restrict__ out)
{
    if (blockIdx.x < FILL_BLOCKS) {
        // ---------------- fill role ----------------
        int i = blockIdx.x * 256 + threadIdx.x;   // quad index
        if (i < N_EDGES / 4) {
            int4 r = reinterpret_cast<const int4*>(recv_idx)[i];
            int e0 = i * 4;
            int p0 = atomicAdd(&g_cnt[r.x], 1);
            int p1 = atomicAdd(&g_cnt[r.y], 1);
            int p2 = atomicAdd(&g_cnt[r.z], 1);
            int p3 = atomicAdd(&g_cnt[r.w], 1);
            g_eid2[r.x * CAP + p0] = e0;
            g_eid2[r.y * CAP + p1] = e0 + 1;
            g_eid2[r.z * CAP + p2] = e0 + 2;
            g_eid2[r.w * CAP + p3] = e0 + 3;
        }
        return;
    }

    // ---------------- node-half GEMM role ----------------
    __shared__ __align__(16) float Ws[KC * D_FEAT];     // 8 KB
    __shared__ __align__(16) float Xs[NT * KC];         // 2 KB

    const int tid  = threadIdx.x;
    const int lane = tid & 31;
    const int wid  = tid >> 5;
    const int n0   = (blockIdx.x - FILL_BLOCKS) * NT;

    unsigned long long acc2[4][2];
    #pragma unroll
    for (int i = 0; i < 4; i++) { acc2[i][0] = 0ull; acc2[i][1] = 0ull; }

    for (int k0 = 0; k0 < D_FEAT; k0 += KC) {
        {   // stage W[k0 : k0+KC, :]
            const float4* src = reinterpret_cast<const float4*>(W + k0 * D_FEAT);
            float4* dst = reinterpret_cast<float4*>(Ws);
            dst[tid]       = src[tid];
            dst[tid + 256] = src[tid + 256];
        }
        #pragma unroll
        for (int i = tid; i < NT * KC; i += 256) {
            int n = i >> 4;
            int k = i & (KC - 1);
            int gn = n0 + n;
            Xs[i] = (gn < N_NODES) ? node_feat[(size_t)gn * D_FEAT + k0 + k] : 0.f;
        }
        __syncthreads();
        #pragma unroll
        for (int kk = 0; kk < KC; kk++) {
            const unsigned long long* wrow =
                reinterpret_cast<const unsigned long long*>(&Ws[kk * D_FEAT + lane * 4]);
            unsigned long long wp0 = wrow[0];
            unsigned long long wp1 = wrow[1];
            #pragma unroll
            for (int n = 0; n < 4; n++) {
                unsigned long long xx = dup2(Xs[(wid * 4 + n) * KC + kk]);
                acc2[n][0] = fma2(xx, wp0, acc2[n][0]);
                acc2[n][1] = fma2(xx, wp1, acc2[n][1]);
            }
        }
        __syncthreads();
    }

    float4 bb = *reinterpret_cast<const float4*>(&b[lane * 4]);
    #pragma unroll
    for (int n = 0; n < 4; n++) {
        int gn = n0 + wid * 4 + n;
        if (gn < N_NODES) {
            float2 p0 = *reinterpret_cast<float2*>(&acc2[n][0]);
            float2 p1 = *reinterpret_cast<float2*>(&acc2[n][1]);
            float4 r;
            r.x = p0.x + bb.x;
            r.y = p0.y + bb.y;
            r.z = p1.x + bb.z;
            r.w = p1.y + bb.w;
            *reinterpret_cast<float4*>(out + (size_t)gn * D_FEAT + lane * 4) = r;
        }
    }
}

// ---------------------------------------------------------------------------
// Kernel 2: fused gather + agg-half GEMM, accumulating into out.
// Identical gather machinery to the 97.0us champion (NT=32, 256 thr, 313
// blocks, smem-staged eids, 16 rows in flight, dynamic node queue). GEMM
// phase is HALF the size now (only K in [128,256) from AggS) and reads the
// partial result written by prep_kernel (L2-resident) instead of bias.
// ---------------------------------------------------------------------------
__global__ __launch_bounds__(256) void fused_kernel(
    const float* __restrict__ edge_feat,
    const float* __restrict__ W,
    float* __restrict__ out)
{
    __shared__ __align__(16) float AggS[NT * D_FEAT];   // 16 KB
    __shared__ __align__(16) float Ws[KC * D_FEAT];     //  8 KB
    __shared__ int eidS[8][CAP];                        //  5 KB
    __shared__ int qctr;

    const int tid  = threadIdx.x;
    const int lane = tid & 31;
    const int wid  = tid >> 5;
    const int n0   = blockIdx.x * NT;

    if (tid == 0) qctr = 0;
    __syncthreads();

    // ---------------- Phase A: gather (dynamic queue) ----------------
    for (;;) {
        int pos;
        if (lane == 0) pos = atomicAdd(&qctr, 1);
        pos = __shfl_sync(0xFFFFFFFFu, pos, 0);
        if (pos >= NT) break;

        int gn = n0 + pos;
        float4 acc = make_float4(0.f, 0.f, 0.f, 0.f);
        if (gn < N_NODES) {
            const int* bucket = g_eid2 + (size_t)gn * CAP;
            int cnt = g_cnt[gn];
            if (cnt > CAP) cnt = CAP;
            for (int base = lane; base < cnt; base += 32)
                eidS[wid][base] = bucket[base];
            __syncwarp();

            int t = 0;
            for (; t + 16 <= cnt; t += 16) {
                int ea[8], eb[8];
                #pragma unroll
                for (int u = 0; u < 8; u++) ea[u] = eidS[wid][t + u];
                #pragma unroll
                for (int u = 0; u < 8; u++) eb[u] = eidS[wid][t + 8 + u];
                float4 va[8], vb[8];
                #pragma unroll
                for (int u = 0; u < 8; u++)
                    va[u] = *reinterpret_cast<const float4*>(
                        edge_feat + (size_t)ea[u] * D_FEAT + lane * 4);
                #pragma unroll
                for (int u = 0; u < 8; u++)
                    vb[u] = *reinterpret_cast<const float4*>(
                        edge_feat + (size_t)eb[u] * D_FEAT + lane * 4);
                #pragma unroll
                for (int u = 0; u < 8; u++) {
                    acc.x += va[u].x; acc.y += va[u].y;
                    acc.z += va[u].z; acc.w += va[u].w;
                }
                #pragma unroll
                for (int u = 0; u < 8; u++) {
                    acc.x += vb[u].x; acc.y += vb[u].y;
                    acc.z += vb[u].z; acc.w += vb[u].w;
                }
            }
            for (; t + 4 <= cnt; t += 4) {
                int e[4];
                #pragma unroll
                for (int u = 0; u < 4; u++) e[u] = eidS[wid][t + u];
                float4 v[4];
                #pragma unroll
                for (int u = 0; u < 4; u++)
                    v[u] = *reinterpret_cast<const float4*>(
                        edge_feat + (size_t)e[u] * D_FEAT + lane * 4);
                #pragma unroll
                for (int u = 0; u < 4; u++) {
                    acc.x += v[u].x; acc.y += v[u].y;
                    acc.z += v[u].z; acc.w += v[u].w;
                }
            }
            for (; t < cnt; t++) {
                int e = eidS[wid][t];
                float4 v = *reinterpret_cast<const float4*>(
                    edge_feat + (size_t)e * D_FEAT + lane * 4);
                acc.x += v.x; acc.y += v.y; acc.z += v.z; acc.w += v.w;
            }
            __syncwarp();
        }
        *reinterpret_cast<float4*>(&AggS[pos * D_FEAT + lane * 4]) = acc;
    }
    __syncthreads();

    // Re-zero this block's cursors for the next call.
    if (tid < NT) {
        int gn = n0 + tid;
        if (gn < N_NODES) g_cnt[gn] = 0;
    }

    // ---------------- Phase B: agg-half GEMM only ----------------
    unsigned long long acc2[4][2];
    #pragma unroll
    for (int i = 0; i < 4; i++) { acc2[i][0] = 0ull; acc2[i][1] = 0ull; }

    for (int k0 = 0; k0 < D_FEAT; k0 += KC) {
        {   // stage W[128 + k0 : 128 + k0 + KC, :]
            const float4* src = reinterpret_cast<const float4*>(W + (D_FEAT + k0) * D_FEAT);
            float4* dst = reinterpret_cast<float4*>(Ws);
            dst[tid]       = src[tid];
            dst[tid + 256] = src[tid + 256];
        }
        __syncthreads();
        #pragma unroll
        for (int kk = 0; kk < KC; kk++) {
            const unsigned long long* wrow =
                reinterpret_cast<const unsigned long long*>(&Ws[kk * D_FEAT + lane * 4]);
            unsigned long long wp0 = wrow[0];
            unsigned long long wp1 = wrow[1];
            #pragma unroll
            for (int n = 0; n < 4; n++) {
                unsigned long long xx = dup2(AggS[(wid * 4 + n) * D_FEAT + k0 + kk]);
                acc2[n][0] = fma2(xx, wp0, acc2[n][0]);
                acc2[n][1] = fma2(xx, wp1, acc2[n][1]);
            }
        }
        __syncthreads();
    }

    // Epilogue: out += acc  (out holds node_feat@W_top + b from prep_kernel)
    #pragma unroll
    for (int n = 0; n < 4; n++) {
        int gn = n0 + wid * 4 + n;
        if (gn < N_NODES) {
            float4 o = *reinterpret_cast<float4*>(out + (size_t)gn * D_FEAT + lane * 4);
            float2 p0 = *reinterpret_cast<float2*>(&acc2[n][0]);
            float2 p1 = *reinterpret_cast<float2*>(&acc2[n][1]);
            float4 r;
            r.x = o.x + p0.x;
            r.y = o.y + p0.y;
            r.z = o.z + p1.x;
            r.w = o.w + p1.y;
            *reinterpret_cast<float4*>(out + (size_t)gn * D_FEAT + lane * 4) = r;
        }
    }
}

// ---------------------------------------------------------------------------
extern "C" void kernel_launch(void* const* d_in, const int* in_sizes, int n_in,
                              void* d_out, int out_size) {
    const float* edge_feat = (const float*)d_in[0];
    const float* node_feat = (const float*)d_in[1];
    const int*   recv_idx  = (const int*)d_in[2];
    const float* W         = (const float*)d_in[3];
    const float* b         = (const float*)d_in[4];
    float*       out       = (float*)d_out;

    prep_kernel<<<FILL_BLOCKS + GEMM_BLOCKS, 256>>>(recv_idx, node_feat, W, b, out);
    fused_kernel<<<GEMM_BLOCKS, 256>>>(edge_feat, W, out);
}